// round 11
// baseline (speedup 1.0000x reference)
#include <cuda_runtime.h>
#include <cuda_fp16.h>
#include <cstdint>

#define LN_EPS 1e-6f

// Fixed problem shape: M = S*B = 32768, K = H = 1024, N = F = 1024
#define DIM_M 32768
#define DIM_K 1024
#define DIM_N 1024

// Scratch (allocation-free rule: __device__ globals)
__device__ __half g_Ah[(size_t)DIM_M * DIM_K];  // fp16 ln_out (GEMM A, row-major)
__device__ __half g_Bh[(size_t)DIM_K * DIM_N];  // fp16 kernel  (GEMM B, K-major)

// ============================================================
// helpers
// ============================================================
__device__ __forceinline__ void cp16(uint32_t smem_dst, const void* g) {
    asm volatile("cp.async.cg.shared.global [%0], [%1], 16;\n" :: "r"(smem_dst), "l"(g));
}
__device__ __forceinline__ void cp_commit() {
    asm volatile("cp.async.commit_group;\n");
}
__device__ __forceinline__ void ldsm4(uint32_t& r0, uint32_t& r1, uint32_t& r2,
                                      uint32_t& r3, uint32_t addr) {
    asm volatile("ldmatrix.sync.aligned.m8n8.x4.shared.b16 {%0,%1,%2,%3}, [%4];"
                 : "=r"(r0), "=r"(r1), "=r"(r2), "=r"(r3) : "r"(addr));
}
__device__ __forceinline__ void ldsm4t(uint32_t& r0, uint32_t& r1, uint32_t& r2,
                                       uint32_t& r3, uint32_t addr) {
    asm volatile("ldmatrix.sync.aligned.m8n8.x4.trans.shared.b16 {%0,%1,%2,%3}, [%4];"
                 : "=r"(r0), "=r"(r1), "=r"(r2), "=r"(r3) : "r"(addr));
}
__device__ __forceinline__ void mma_f16(float* c, const uint32_t* a, const uint32_t* b) {
    asm volatile(
        "mma.sync.aligned.m16n8k16.row.col.f32.f16.f16.f32 "
        "{%0,%1,%2,%3}, {%4,%5,%6,%7}, {%8,%9}, {%0,%1,%2,%3};\n"
        : "+f"(c[0]), "+f"(c[1]), "+f"(c[2]), "+f"(c[3])
        : "r"(a[0]), "r"(a[1]), "r"(a[2]), "r"(a[3]), "r"(b[0]), "r"(b[1]));
}

// ============================================================
// prep kernel: blocks [0, M)        -> LayerNorm rows
//              blocks [M, M + 1024) -> fp16-round weight (elementwise)
// ln_out written exact fp32; fp16 copy of it goes to g_Ah.
// ============================================================
__global__ void prep_kernel(const float* __restrict__ x,
                            const float* __restrict__ scale,
                            const float* __restrict__ bias,
                            const float* __restrict__ B,
                            float* __restrict__ ln_out) {
    if (blockIdx.x < DIM_M) {
        int row = blockIdx.x;
        const float4* xr = reinterpret_cast<const float4*>(x + (size_t)row * DIM_K);
        float4 v = xr[threadIdx.x];

        float s  = v.x + v.y + v.z + v.w;
        float sq = v.x * v.x + v.y * v.y + v.z * v.z + v.w * v.w;
        #pragma unroll
        for (int o = 16; o > 0; o >>= 1) {
            s  += __shfl_xor_sync(0xffffffffu, s,  o);
            sq += __shfl_xor_sync(0xffffffffu, sq, o);
        }
        __shared__ float ssum[8], ssq[8];
        int wid = threadIdx.x >> 5, lid = threadIdx.x & 31;
        if (lid == 0) { ssum[wid] = s; ssq[wid] = sq; }
        __syncthreads();
        s = 0.f; sq = 0.f;
        #pragma unroll
        for (int i = 0; i < 8; i++) { s += ssum[i]; sq += ssq[i]; }

        float invH = 1.0f / (float)DIM_K;
        float mu   = s * invH;
        float var  = sq * invH - mu * mu;
        float rstd = rsqrtf(var + LN_EPS);

        float4 sc = reinterpret_cast<const float4*>(scale)[threadIdx.x];
        float4 bi = reinterpret_cast<const float4*>(bias)[threadIdx.x];
        float4 o;
        o.x = (v.x - mu) * rstd * sc.x + bi.x;
        o.y = (v.y - mu) * rstd * sc.y + bi.y;
        o.z = (v.z - mu) * rstd * sc.z + bi.z;
        o.w = (v.w - mu) * rstd * sc.w + bi.w;
        reinterpret_cast<float4*>(ln_out + (size_t)row * DIM_K)[threadIdx.x] = o;

        __half2 p0 = __floats2half2_rn(o.x, o.y);
        __half2 p1 = __floats2half2_rn(o.z, o.w);
        uint2 pk;
        pk.x = *reinterpret_cast<uint32_t*>(&p0);
        pk.y = *reinterpret_cast<uint32_t*>(&p1);
        reinterpret_cast<uint2*>(g_Ah + (size_t)row * DIM_K)[threadIdx.x] = pk;
    } else {
        // elementwise fp16 round of the weight (keeps K-major layout)
        size_t base = (size_t)(blockIdx.x - DIM_M) * 1024 + threadIdx.x * 4;
        float4 v = *reinterpret_cast<const float4*>(B + base);
        __half2 p0 = __floats2half2_rn(v.x, v.y);
        __half2 p1 = __floats2half2_rn(v.z, v.w);
        uint2 pk;
        pk.x = *reinterpret_cast<uint32_t*>(&p0);
        pk.y = *reinterpret_cast<uint32_t*>(&p1);
        *reinterpret_cast<uint2*>(g_Bh + base) = pk;
    }
}

// ============================================================
// FP16 GEMM (mma.m16n8k16 + ldmatrix): C[M,N] = g_Ah * g_Bh
// BM=128 BN=256 BK=64; 256 threads (8 warps 2x4), warp tile
// 64x64 (1.5x fewer LDSM bytes per FLOP vs 64x32 -> relieves the
// smem crossbar seen at L1=63%); 4-stage cp.async ring, 1 CTA/SM,
// one barrier per tile, cross-tile fragment preload kept.
// ============================================================
#define STAGES 4
#define BM 128
#define BN 256
#define BKH 64                              // k-halfs per tile
#define A_ROW_B 144                         // 64 halfs (128B) + 16B pad
#define B_ROW_B 528                         // 256 halfs (512B) + 16B pad
#define TILE_A (BM * A_ROW_B)               // 18432
#define TILE_BB (BKH * B_ROW_B)             // 33792
#define STAGE_B (TILE_A + TILE_BB)          // 52224
#define GEMM_SMEM (STAGES * STAGE_B)        // 208896 (<= 227KB dynamic)

__device__ __forceinline__ void load_stage(uint32_t sb, int slot, int kt,
                                           const __half* Ag, const __half* Bg, int tid) {
    uint32_t st = sb + slot * STAGE_B;
    const int k0 = kt * BKH;
    #pragma unroll
    for (int i = 0; i < 4; i++) {          // A: 128 rows x 8 chunks = 1024 / 256 thr
        int c = i * 256 + tid;
        int r = c >> 3, j = c & 7;
        cp16(st + (uint32_t)(r * A_ROW_B + j * 16),
             Ag + (size_t)r * DIM_K + k0 + j * 8);
    }
    #pragma unroll
    for (int i = 0; i < 8; i++) {          // B: 64 rows x 32 chunks = 2048 / 256 thr
        int c = i * 256 + tid;
        int r = c >> 5, j = c & 31;
        cp16(st + TILE_A + (uint32_t)(r * B_ROW_B + j * 16),
             Bg + (size_t)(k0 + r) * DIM_N + j * 8);
    }
    cp_commit();
}

__device__ __forceinline__ void ldsm_frags(uint32_t awarp, uint32_t bwarp, int kc,
                                           uint32_t a[4][4], uint32_t b[4][4]) {
    #pragma unroll
    for (int mt = 0; mt < 4; mt++)
        ldsm4(a[mt][0], a[mt][1], a[mt][2], a[mt][3],
              awarp + (uint32_t)(mt * 16) * A_ROW_B + kc * 32);
    #pragma unroll
    for (int g = 0; g < 4; g++)            // each x4.trans: 16 n-cols
        ldsm4t(b[g][0], b[g][1], b[g][2], b[g][3],
               bwarp + (uint32_t)(kc * 16) * B_ROW_B + g * 32);
}

__global__ void __launch_bounds__(256, 1)
gemm_f16(float* __restrict__ C) {
    extern __shared__ __align__(1024) char smem[];
    uint32_t sb;
    asm("{ .reg .u64 t; cvta.to.shared.u64 t, %1; cvt.u32.u64 %0, t; }"
        : "=r"(sb) : "l"(smem));

    const int tid  = threadIdx.x;
    const int warp = tid >> 5, lane = tid & 31;
    const int wm = warp >> 2;        // 0..1 -> m offset wm*64
    const int wn = warp & 3;         // 0..3 -> n offset wn*64
    const int gid = lane >> 2;       // 0..7
    const int tig = lane & 3;        // 0..3

    // A (non-trans x4): rows l&15, col-group (l>>4)*16B
    const uint32_t aoff = (uint32_t)((lane & 15) * A_ROW_B + (lane >> 4) * 16) +
                          (uint32_t)(wm * 64) * A_ROW_B;
    // B (trans x4): k-rows (l&7)+8*((l>>3)&1), n-group (l>>4)*16B; warp n = wn*64 halfs
    const uint32_t boff = (uint32_t)(((lane & 7) + 8 * ((lane >> 3) & 1)) * B_ROW_B +
                                     (lane >> 4) * 16) + (uint32_t)(wn * 128) + TILE_A;

    const int bm = blockIdx.y, bn = blockIdx.x;
    const __half* Ag = g_Ah + (size_t)bm * BM * DIM_K;
    const __half* Bg = g_Bh + bn * BN;

    float acc[4][8][4];   // [mt][nf][reg]
    #pragma unroll
    for (int i = 0; i < 4; i++)
        #pragma unroll
        for (int j = 0; j < 8; j++)
            #pragma unroll
            for (int r = 0; r < 4; r++) acc[i][j][r] = 0.f;

    const int T = DIM_K / BKH;   // 16
    load_stage(sb, 0, 0, Ag, Bg, tid);
    load_stage(sb, 1, 1, Ag, Bg, tid);
    load_stage(sb, 2, 2, Ag, Bg, tid);

    // fragment buffers persist ACROSS tiles (cross-tile rolling pipeline)
    uint32_t a[2][4][4], b[2][4][4];

    for (int t = 0; t < T; t++) {
        // pending here = {t, t+1, t+2}; wait_group 1 completes t AND t+1
        // (t+1 is what the cross-tile preload reads), leaves t+2 in flight.
        asm volatile("cp.async.wait_group 1;\n");
        __syncthreads();

        const uint32_t as    = sb + (t & 3) * STAGE_B;
        const uint32_t awarp = as + aoff;
        const uint32_t bwarp = as + boff;

        if (t == 0) ldsm_frags(awarp, bwarp, 0, a[0], b[0]);  // prologue only

        #pragma unroll
        for (int kc = 0; kc < 4; kc++) {
            const int cur = kc & 1, nxt = cur ^ 1;
            if (kc == 1) {
                // refill burst: kc0's 32 HMMAs already queued hide the
                // LDGSTS issue. Slot (t+3)%4 held tile t-1 (finished before
                // this iteration's barrier).
                if (t + 3 < T) load_stage(sb, (t + 3) & 3, t + 3, Ag, Bg, tid);
                else           cp_commit();
            }
            if (kc < 3) {
                ldsm_frags(awarp, bwarp, kc + 1, a[nxt], b[nxt]);
            } else if (t + 1 < T) {
                // preload NEXT tile's kc0 from slot (t+1)%4 (guaranteed by
                // this iteration's wait_group 1 + barrier; refill targets
                // (t+3)%4, disjoint). Buffer parity self-aligns.
                const uint32_t as2 = sb + ((t + 1) & 3) * STAGE_B;
                ldsm_frags(as2 + aoff, as2 + boff, 0, a[nxt], b[nxt]);
            }
            #pragma unroll
            for (int mt = 0; mt < 4; mt++)
                #pragma unroll
                for (int nf = 0; nf < 8; nf++)
                    mma_f16(acc[mt][nf], a[cur][mt], &b[cur][nf >> 1][(nf & 1) * 2]);
        }
        // no trailing barrier: next iteration's wait+sync covers the hazard.
    }

    // epilogue: direct float2 stores
    float* Cb = C + (size_t)(bm * BM) * DIM_N + bn * BN;
    #pragma unroll
    for (int mt = 0; mt < 4; mt++) {
        const int m = wm * 64 + mt * 16 + gid;
        #pragma unroll
        for (int nf = 0; nf < 8; nf++) {
            const int n = wn * 64 + nf * 8 + 2 * tig;
            const float* a4 = acc[mt][nf];
            *reinterpret_cast<float2*>(Cb + (size_t)m * DIM_N + n) =
                make_float2(a4[0], a4[1]);
            *reinterpret_cast<float2*>(Cb + (size_t)(m + 8) * DIM_N + n) =
                make_float2(a4[2], a4[3]);
        }
    }
}

// ============================================================
// launch
// ============================================================
extern "C" void kernel_launch(void* const* d_in, const int* in_sizes, int n_in,
                              void* d_out, int out_size) {
    const float* x       = (const float*)d_in[0];  // (S,B,H)
    const float* scale   = (const float*)d_in[1];  // (H,)
    const float* ln_bias = (const float*)d_in[2];  // (H,)
    const float* kern    = (const float*)d_in[3];  // (H,F)

    const int H = in_sizes[1];
    const int M = in_sizes[0] / H;   // 32768
    const int F = in_sizes[3] / H;   // 1024

    float* out    = (float*)d_out;             // (M,F) first
    float* ln_out = out + (size_t)M * F;       // (M,H) second

    prep_kernel<<<M + (H * F) / 1024, 256>>>(x, scale, ln_bias, kern, ln_out);

    cudaFuncSetAttribute(gemm_f16, cudaFuncAttributeMaxDynamicSharedMemorySize, GEMM_SMEM);
    gemm_f16<<<dim3(F / BN, M / BM), 256, GEMM_SMEM>>>(out);
}

// round 12
// speedup vs baseline: 1.0460x; 1.0460x over previous
#include <cuda_runtime.h>
#include <cuda_fp16.h>
#include <cstdint>

#define LN_EPS 1e-6f

// Fixed problem shape: M = S*B = 32768, K = H = 1024, N = F = 1024
#define DIM_M 32768
#define DIM_K 1024
#define DIM_N 1024

// Scratch (allocation-free rule: __device__ globals)
__device__ __half g_Ah[(size_t)DIM_M * DIM_K];  // fp16 ln_out (GEMM A, row-major)
__device__ __half g_Bh[(size_t)DIM_K * DIM_N];  // fp16 kernel  (GEMM B, K-major)

// ============================================================
// helpers
// ============================================================
__device__ __forceinline__ void cp16(uint32_t smem_dst, const void* g) {
    asm volatile("cp.async.cg.shared.global [%0], [%1], 16;\n" :: "r"(smem_dst), "l"(g));
}
__device__ __forceinline__ void cp_commit() {
    asm volatile("cp.async.commit_group;\n");
}
__device__ __forceinline__ void ldsm4(uint32_t& r0, uint32_t& r1, uint32_t& r2,
                                      uint32_t& r3, uint32_t addr) {
    asm volatile("ldmatrix.sync.aligned.m8n8.x4.shared.b16 {%0,%1,%2,%3}, [%4];"
                 : "=r"(r0), "=r"(r1), "=r"(r2), "=r"(r3) : "r"(addr));
}
__device__ __forceinline__ void ldsm4t(uint32_t& r0, uint32_t& r1, uint32_t& r2,
                                       uint32_t& r3, uint32_t addr) {
    asm volatile("ldmatrix.sync.aligned.m8n8.x4.trans.shared.b16 {%0,%1,%2,%3}, [%4];"
                 : "=r"(r0), "=r"(r1), "=r"(r2), "=r"(r3) : "r"(addr));
}
__device__ __forceinline__ void mma_f16(float* c, const uint32_t* a, const uint32_t* b) {
    asm volatile(
        "mma.sync.aligned.m16n8k16.row.col.f32.f16.f16.f32 "
        "{%0,%1,%2,%3}, {%4,%5,%6,%7}, {%8,%9}, {%0,%1,%2,%3};\n"
        : "+f"(c[0]), "+f"(c[1]), "+f"(c[2]), "+f"(c[3])
        : "r"(a[0]), "r"(a[1]), "r"(a[2]), "r"(a[3]), "r"(b[0]), "r"(b[1]));
}

// ============================================================
// prep kernel: blocks [0, M)        -> LayerNorm rows
//              blocks [M, M + 1024) -> fp16-round weight (elementwise)
// ln_out written exact fp32; fp16 copy of it goes to g_Ah.
// ============================================================
__global__ void prep_kernel(const float* __restrict__ x,
                            const float* __restrict__ scale,
                            const float* __restrict__ bias,
                            const float* __restrict__ B,
                            float* __restrict__ ln_out) {
    if (blockIdx.x < DIM_M) {
        int row = blockIdx.x;
        const float4* xr = reinterpret_cast<const float4*>(x + (size_t)row * DIM_K);
        float4 v = xr[threadIdx.x];

        float s  = v.x + v.y + v.z + v.w;
        float sq = v.x * v.x + v.y * v.y + v.z * v.z + v.w * v.w;
        #pragma unroll
        for (int o = 16; o > 0; o >>= 1) {
            s  += __shfl_xor_sync(0xffffffffu, s,  o);
            sq += __shfl_xor_sync(0xffffffffu, sq, o);
        }
        __shared__ float ssum[8], ssq[8];
        int wid = threadIdx.x >> 5, lid = threadIdx.x & 31;
        if (lid == 0) { ssum[wid] = s; ssq[wid] = sq; }
        __syncthreads();
        s = 0.f; sq = 0.f;
        #pragma unroll
        for (int i = 0; i < 8; i++) { s += ssum[i]; sq += ssq[i]; }

        float invH = 1.0f / (float)DIM_K;
        float mu   = s * invH;
        float var  = sq * invH - mu * mu;
        float rstd = rsqrtf(var + LN_EPS);

        float4 sc = reinterpret_cast<const float4*>(scale)[threadIdx.x];
        float4 bi = reinterpret_cast<const float4*>(bias)[threadIdx.x];
        float4 o;
        o.x = (v.x - mu) * rstd * sc.x + bi.x;
        o.y = (v.y - mu) * rstd * sc.y + bi.y;
        o.z = (v.z - mu) * rstd * sc.z + bi.z;
        o.w = (v.w - mu) * rstd * sc.w + bi.w;
        reinterpret_cast<float4*>(ln_out + (size_t)row * DIM_K)[threadIdx.x] = o;

        __half2 p0 = __floats2half2_rn(o.x, o.y);
        __half2 p1 = __floats2half2_rn(o.z, o.w);
        uint2 pk;
        pk.x = *reinterpret_cast<uint32_t*>(&p0);
        pk.y = *reinterpret_cast<uint32_t*>(&p1);
        reinterpret_cast<uint2*>(g_Ah + (size_t)row * DIM_K)[threadIdx.x] = pk;
    } else {
        // elementwise fp16 round of the weight (keeps K-major layout)
        size_t base = (size_t)(blockIdx.x - DIM_M) * 1024 + threadIdx.x * 4;
        float4 v = *reinterpret_cast<const float4*>(B + base);
        __half2 p0 = __floats2half2_rn(v.x, v.y);
        __half2 p1 = __floats2half2_rn(v.z, v.w);
        uint2 pk;
        pk.x = *reinterpret_cast<uint32_t*>(&p0);
        pk.y = *reinterpret_cast<uint32_t*>(&p1);
        *reinterpret_cast<uint2*>(g_Bh + base) = pk;
    }
}

// ============================================================
// FP16 GEMM (mma.m16n8k16 + ldmatrix): C[M,N] = g_Ah * g_Bh
// BM=BN=128 BK=64; 128 threads (4 warps, 2x2), warp tile 64x64
// (47.5 B/kFLOP crossbar ratio -> ~76 B/cyc at full tensor rate),
// 3-stage cp.async ring -> 107KB smem -> 2 INDEPENDENT CTAs/SM
// (one CTA computes through the other's barrier bubbles).
// Cross-tile kc0 fragment preload + kc1 refill burst kept.
// ============================================================
#define STAGES 3
#define BM 128
#define BN 128
#define BKH 64                              // k-halfs per tile
#define A_ROW_B 144                         // 64 halfs (128B) + 16B pad
#define B_ROW_B 272                         // 128 halfs (256B) + 16B pad
#define TILE_A (BM * A_ROW_B)               // 18432
#define TILE_BB (BKH * B_ROW_B)             // 17408
#define STAGE_B (TILE_A + TILE_BB)          // 35840
#define GEMM_SMEM (STAGES * STAGE_B)        // 107520 -> 2 CTAs/SM

__device__ __forceinline__ void load_stage(uint32_t sb, int slot, int kt,
                                           const __half* Ag, const __half* Bg, int tid) {
    uint32_t st = sb + slot * STAGE_B;
    const int k0 = kt * BKH;
    #pragma unroll
    for (int i = 0; i < 8; i++) {          // A: 128 rows x 8 chunks = 1024 / 128 thr
        int c = i * 128 + tid;
        int r = c >> 3, j = c & 7;
        cp16(st + (uint32_t)(r * A_ROW_B + j * 16),
             Ag + (size_t)r * DIM_K + k0 + j * 8);
    }
    #pragma unroll
    for (int i = 0; i < 8; i++) {          // B: 64 rows x 16 chunks = 1024 / 128 thr
        int c = i * 128 + tid;
        int r = c >> 4, j = c & 15;
        cp16(st + TILE_A + (uint32_t)(r * B_ROW_B + j * 16),
             Bg + (size_t)(k0 + r) * DIM_N + j * 8);
    }
    cp_commit();
}

__device__ __forceinline__ void ldsm_frags(uint32_t awarp, uint32_t bwarp, int kc,
                                           uint32_t a[4][4], uint32_t b[4][4]) {
    #pragma unroll
    for (int mt = 0; mt < 4; mt++)
        ldsm4(a[mt][0], a[mt][1], a[mt][2], a[mt][3],
              awarp + (uint32_t)(mt * 16) * A_ROW_B + kc * 32);
    #pragma unroll
    for (int g = 0; g < 4; g++)            // each x4.trans: 16 n-cols
        ldsm4t(b[g][0], b[g][1], b[g][2], b[g][3],
               bwarp + (uint32_t)(kc * 16) * B_ROW_B + g * 32);
}

__global__ void __launch_bounds__(128, 2)
gemm_f16(float* __restrict__ C) {
    extern __shared__ __align__(1024) char smem[];
    uint32_t sb;
    asm("{ .reg .u64 t; cvta.to.shared.u64 t, %1; cvt.u32.u64 %0, t; }"
        : "=r"(sb) : "l"(smem));

    const int tid  = threadIdx.x;
    const int warp = tid >> 5, lane = tid & 31;
    const int wm = warp >> 1;        // 0..1 -> m offset wm*64
    const int wn = warp & 1;         // 0..1 -> n offset wn*64
    const int gid = lane >> 2;       // 0..7
    const int tig = lane & 3;        // 0..3

    // A (non-trans x4): rows l&15, col-group (l>>4)*16B
    const uint32_t aoff = (uint32_t)((lane & 15) * A_ROW_B + (lane >> 4) * 16) +
                          (uint32_t)(wm * 64) * A_ROW_B;
    // B (trans x4): k-rows (l&7)+8*((l>>3)&1), n-group (l>>4)*16B; warp n = wn*64 halfs
    const uint32_t boff = (uint32_t)(((lane & 7) + 8 * ((lane >> 3) & 1)) * B_ROW_B +
                                     (lane >> 4) * 16) + (uint32_t)(wn * 128) + TILE_A;

    const int bm = blockIdx.y, bn = blockIdx.x;
    const __half* Ag = g_Ah + (size_t)bm * BM * DIM_K;
    const __half* Bg = g_Bh + bn * BN;

    float acc[4][8][4];   // [mt][nf][reg]
    #pragma unroll
    for (int i = 0; i < 4; i++)
        #pragma unroll
        for (int j = 0; j < 8; j++)
            #pragma unroll
            for (int r = 0; r < 4; r++) acc[i][j][r] = 0.f;

    const int T = DIM_K / BKH;   // 16
    load_stage(sb, 0, 0, Ag, Bg, tid);
    load_stage(sb, 1, 1, Ag, Bg, tid);

    // fragment buffers persist ACROSS tiles (cross-tile rolling pipeline)
    uint32_t a[2][4][4], b[2][4][4];

    for (int t = 0; t < T; t++) {
        // pending = {t, t+1}; wait_group 0 completes both (t+1 is what the
        // cross-tile preload reads; it was issued a full tile ago).
        asm volatile("cp.async.wait_group 0;\n");
        __syncthreads();

        const uint32_t as    = sb + (t % 3) * STAGE_B;
        const uint32_t awarp = as + aoff;
        const uint32_t bwarp = as + boff;

        if (t == 0) ldsm_frags(awarp, bwarp, 0, a[0], b[0]);  // prologue only

        #pragma unroll
        for (int kc = 0; kc < 4; kc++) {
            const int cur = kc & 1, nxt = cur ^ 1;
            if (kc == 1) {
                // refill burst: kc0's 32 HMMAs already queued hide the
                // LDGSTS issue. Slot (t+2)%3 held tile t-1 (all warps done
                // with it before this iteration's barrier).
                if (t + 2 < T) load_stage(sb, (t + 2) % 3, t + 2, Ag, Bg, tid);
                else           cp_commit();
            }
            if (kc < 3) {
                ldsm_frags(awarp, bwarp, kc + 1, a[nxt], b[nxt]);
            } else if (t + 1 < T) {
                // preload NEXT tile's kc0 from slot (t+1)%3 (visible since
                // this iteration's wait 0 + barrier; refill targets
                // (t+2)%3, disjoint). Buffer parity self-aligns.
                const uint32_t as2 = sb + ((t + 1) % 3) * STAGE_B;
                ldsm_frags(as2 + aoff, as2 + boff, 0, a[nxt], b[nxt]);
            }
            #pragma unroll
            for (int mt = 0; mt < 4; mt++)
                #pragma unroll
                for (int nf = 0; nf < 8; nf++)
                    mma_f16(acc[mt][nf], a[cur][mt], &b[cur][nf >> 1][(nf & 1) * 2]);
        }
        // no trailing barrier: next iteration's wait+sync covers the hazard.
    }

    // epilogue: direct float2 stores
    float* Cb = C + (size_t)(bm * BM) * DIM_N + bn * BN;
    #pragma unroll
    for (int mt = 0; mt < 4; mt++) {
        const int m = wm * 64 + mt * 16 + gid;
        #pragma unroll
        for (int nf = 0; nf < 8; nf++) {
            const int n = wn * 64 + nf * 8 + 2 * tig;
            const float* a4 = acc[mt][nf];
            *reinterpret_cast<float2*>(Cb + (size_t)m * DIM_N + n) =
                make_float2(a4[0], a4[1]);
            *reinterpret_cast<float2*>(Cb + (size_t)(m + 8) * DIM_N + n) =
                make_float2(a4[2], a4[3]);
        }
    }
}

// ============================================================
// launch
// ============================================================
extern "C" void kernel_launch(void* const* d_in, const int* in_sizes, int n_in,
                              void* d_out, int out_size) {
    const float* x       = (const float*)d_in[0];  // (S,B,H)
    const float* scale   = (const float*)d_in[1];  // (H,)
    const float* ln_bias = (const float*)d_in[2];  // (H,)
    const float* kern    = (const float*)d_in[3];  // (H,F)

    const int H = in_sizes[1];
    const int M = in_sizes[0] / H;   // 32768
    const int F = in_sizes[3] / H;   // 1024

    float* out    = (float*)d_out;             // (M,F) first
    float* ln_out = out + (size_t)M * F;       // (M,H) second

    prep_kernel<<<M + (H * F) / 1024, 256>>>(x, scale, ln_bias, kern, ln_out);

    cudaFuncSetAttribute(gemm_f16, cudaFuncAttributeMaxDynamicSharedMemorySize, GEMM_SMEM);
    gemm_f16<<<dim3(F / BN, M / BM), 128, GEMM_SMEM>>>(out);
}